// round 16
// baseline (speedup 1.0000x reference)
#include <cuda_runtime.h>
#include <cuda_bf16.h>

#define N_GRID 64
#define N1 65
#define W_FEAT 256
#define NCELLS (N_GRID * N_GRID * N_GRID)   // 262144
#define B_MAX 262144

// Scratch (allocation-free rule: __device__ globals).
// g_hist must be zero at first use: static zero-init gives that, and
// scan_block_kernel resets it each pass so graph replays stay correct.
__device__ int    g_hist[NCELLS];       // zero-initialized
__device__ int    g_offsets[NCELLS];    // chunk-local exclusive prefix
__device__ int    g_blocksums[256];     // RAW chunk totals
__device__ int    g_start[NCELLS + 1];  // global exclusive cell starts
__device__ int    g_cursor[NCELLS];     // scatter cursor (= start, consumed)
__device__ int    g_cell[B_MAX];
__device__ float4 g_pts[B_MAX];         // sorted payload: (x,y,z,bitcast(id))

__global__ void hist_kernel(const float* __restrict__ x, int B) {
    int p = blockIdx.x * blockDim.x + threadIdx.x;
    if (p >= B) return;
    const float scale = (float)N_GRID / 2.0f;
    float rx = (x[p * 3 + 0] + 1.0f) * scale;
    float ry = (x[p * 3 + 1] + 1.0f) * scale;
    float rz = (x[p * 3 + 2] + 1.0f) * scale;
    int ix = min(max((int)floorf(rx), 0), N_GRID - 1);
    int iy = min(max((int)floorf(ry), 0), N_GRID - 1);
    int iz = min(max((int)floorf(rz), 0), N_GRID - 1);
    int cell = (ix * N_GRID + iy) * N_GRID + iz;   // lexicographic = memory order
    g_cell[p] = cell;
    atomicAdd(&g_hist[cell], 1);
}

// 256 blocks x 1024 threads: shuffle-based exclusive scan of each 1024-chunk
// into g_offsets, reset g_hist, emit RAW chunk total.
__global__ void __launch_bounds__(1024) scan_block_kernel() {
    __shared__ int wsum[32];
    int tid = threadIdx.x;
    int lane = tid & 31;
    int wid = tid >> 5;
    int i = blockIdx.x * 1024 + tid;

    int v = g_hist[i];
    int inc = v;
    #pragma unroll
    for (int off = 1; off < 32; off <<= 1) {
        int t = __shfl_up_sync(0xFFFFFFFF, inc, off);
        if (lane >= off) inc += t;
    }
    if (lane == 31) wsum[wid] = inc;
    __syncthreads();
    if (wid == 0) {
        int ws = wsum[lane];
        int winc = ws;
        #pragma unroll
        for (int off = 1; off < 32; off <<= 1) {
            int t = __shfl_up_sync(0xFFFFFFFF, winc, off);
            if (lane >= off) winc += t;
        }
        wsum[lane] = winc - ws;      // exclusive warp prefix
    }
    __syncthreads();
    int excl = inc - v + wsum[wid];
    g_offsets[i] = excl;
    g_hist[i] = 0;                   // ready for next replay
    if (tid == 1023) g_blocksums[blockIdx.x] = excl + v;  // raw chunk total
}

// 1024 blocks x 256 threads. Each block scans the 256 raw chunk totals in
// smem, then writes global cell starts + scatter cursors for its 256 cells.
__global__ void __launch_bounds__(256) finalize_kernel(int B) {
    __shared__ int bs[256];
    __shared__ int wsum[8];
    int tid = threadIdx.x;
    int lane = tid & 31;
    int wid = tid >> 5;

    int raw = g_blocksums[tid];
    int inc = raw;
    #pragma unroll
    for (int off = 1; off < 32; off <<= 1) {
        int t = __shfl_up_sync(0xFFFFFFFF, inc, off);
        if (lane >= off) inc += t;
    }
    if (lane == 31) wsum[wid] = inc;
    __syncthreads();
    if (wid == 0 && lane < 8) {
        int ws = wsum[lane];
        int winc = ws;
        #pragma unroll
        for (int off = 1; off < 8; off <<= 1) {
            int t = __shfl_up_sync(0x000000FF, winc, off);
            if (lane >= off) winc += t;
        }
        wsum[lane] = winc - ws;      // exclusive warp prefix
    }
    __syncthreads();
    bs[tid] = inc - raw + wsum[wid]; // exclusive prefix of chunk totals
    __syncthreads();

    int i = blockIdx.x * 256 + tid;
    int s = g_offsets[i] + bs[i >> 10];
    g_start[i]  = s;
    g_cursor[i] = s;
    if (i == 0) g_start[NCELLS] = B;
}

// 1024 blocks x 256 threads: scatter points as float4 payloads into sorted order.
__global__ void __launch_bounds__(256) scatter_kernel(const float* __restrict__ x, int B) {
    int p = blockIdx.x * blockDim.x + threadIdx.x;
    if (p >= B) return;
    int c = g_cell[p];
    int pos = atomicAdd(&g_cursor[c], 1);
    g_pts[pos] = make_float4(x[p * 3 + 0], x[p * 3 + 1], x[p * 3 + 2],
                             __int_as_float(p));
}

// Thread-per-point scalar grid_value interpolation, in sorted order.
__global__ void __launch_bounds__(256) gridval_kernel(
    const float* __restrict__ grid_value,
    float* __restrict__ out_val,
    int B)
{
    int i = blockIdx.x * blockDim.x + threadIdx.x;
    if (i >= B) return;

    float4 pt = __ldg(&g_pts[i]);
    int p = __float_as_int(pt.w);

    const float scale = (float)N_GRID / 2.0f;
    float rx = (pt.x + 1.0f) * scale;
    float ry = (pt.y + 1.0f) * scale;
    float rz = (pt.z + 1.0f) * scale;

    bool valid = (rx >= 0.0f) && (rx <= (float)N_GRID) &&
                 (ry >= 0.0f) && (ry <= (float)N_GRID) &&
                 (rz >= 0.0f) && (rz <= (float)N_GRID);

    int ix = min(max((int)floorf(rx), 0), N_GRID - 1);
    int iy = min(max((int)floorf(ry), 0), N_GRID - 1);
    int iz = min(max((int)floorf(rz), 0), N_GRID - 1);

    float tx = rx - (float)ix;
    float ty = ry - (float)iy;
    float tz = rz - (float)iz;

    int base = (ix * N1 + iy) * N1 + iz;

    float wx0 = 1.0f - tx, wx1 = tx;
    float wy0 = 1.0f - ty, wy1 = ty;
    float wz0 = 1.0f - tz, wz1 = tz;

    float v000 = __ldg(&grid_value[base]);
    float v001 = __ldg(&grid_value[base + 1]);
    float v010 = __ldg(&grid_value[base + N1]);
    float v011 = __ldg(&grid_value[base + N1 + 1]);
    float v100 = __ldg(&grid_value[base + N1 * N1]);
    float v101 = __ldg(&grid_value[base + N1 * N1 + 1]);
    float v110 = __ldg(&grid_value[base + N1 * N1 + N1]);
    float v111 = __ldg(&grid_value[base + N1 * N1 + N1 + 1]);

    float s = wx0 * wy0 * wz0 * v000 + wx0 * wy0 * wz1 * v001
            + wx0 * wy1 * wz0 * v010 + wx0 * wy1 * wz1 * v011
            + wx1 * wy0 * wz0 * v100 + wx1 * wy0 * wz1 * v101
            + wx1 * wy1 * wz0 * v110 + wx1 * wy1 * wz1 * v111;

    out_val[p] = valid ? s : 0.0f;
}

// Warp per CELL: load the cell's 8 corner rows once (per 128-feature half),
// serve every point in the cell from registers. Full same-cell sharing:
// feature loads drop to (occupied cells / points) = ~0.63x.
__global__ void __launch_bounds__(128) trilerp_kernel(
    const float* __restrict__ grid_feature,
    float* __restrict__ out_feat)
{
    int c = (blockIdx.x * blockDim.x + threadIdx.x) >> 5;   // cell id
    int lane = threadIdx.x & 31;
    if (c >= NCELLS) return;

    int s = g_start[c];
    int e = g_start[c + 1];
    if (s == e) return;          // empty cell

    int iz = c & (N_GRID - 1);
    int iy = (c >> 6) & (N_GRID - 1);
    int ix = c >> 12;
    int base = (ix * N1 + iy) * N1 + iz;

    const float4* bp = (const float4*)(grid_feature + (size_t)base * W_FEAT) + lane;

    #pragma unroll
    for (int half = 0; half < 2; half++) {
        // Load this half's 8 corner float4s once for the whole cell.
        float4 f[8];
        #pragma unroll
        for (int cc = 0; cc < 8; cc++) {
            int off = (((cc >> 2) & 1) * (N1 * N1) + ((cc >> 1) & 1) * N1 + (cc & 1)) * (W_FEAT / 4);
            f[cc] = __ldg(bp + off + half * 32);
        }

        for (int i = s; i < e; i++) {
            float4 pt = __ldg(&g_pts[i]);    // broadcast
            int p = __float_as_int(pt.w);

            const float scale = (float)N_GRID / 2.0f;
            float rx = (pt.x + 1.0f) * scale;
            float ry = (pt.y + 1.0f) * scale;
            float rz = (pt.z + 1.0f) * scale;

            bool valid = (rx >= 0.0f) && (rx <= (float)N_GRID) &&
                         (ry >= 0.0f) && (ry <= (float)N_GRID) &&
                         (rz >= 0.0f) && (rz <= (float)N_GRID);

            float tx = rx - (float)ix;
            float ty = ry - (float)iy;
            float tz = rz - (float)iz;

            float wx0 = 1.0f - tx, wx1 = tx;
            float wy0 = 1.0f - ty, wy1 = ty;
            float wz0 = 1.0f - tz, wz1 = tz;

            float w[8];
            w[0] = wx0 * wy0 * wz0;
            w[1] = wx0 * wy0 * wz1;
            w[2] = wx0 * wy1 * wz0;
            w[3] = wx0 * wy1 * wz1;
            w[4] = wx1 * wy0 * wz0;
            w[5] = wx1 * wy0 * wz1;
            w[6] = wx1 * wy1 * wz0;
            w[7] = wx1 * wy1 * wz1;

            float4 acc = make_float4(0.f, 0.f, 0.f, 0.f);
            #pragma unroll
            for (int cc = 0; cc < 8; cc++) {        // same order as reference
                float wc = w[cc];
                acc.x += wc * f[cc].x; acc.y += wc * f[cc].y;
                acc.z += wc * f[cc].z; acc.w += wc * f[cc].w;
            }
            if (!valid) acc = make_float4(0.f, 0.f, 0.f, 0.f);

            ((float4*)(out_feat + (size_t)p * W_FEAT))[half * 32 + lane] = acc;
        }
    }
}

extern "C" void kernel_launch(void* const* d_in, const int* in_sizes, int n_in,
                              void* d_out, int out_size) {
    const float* x            = (const float*)d_in[0];
    const float* grid_value   = (const float*)d_in[1];
    const float* grid_feature = (const float*)d_in[2];

    int B = in_sizes[0] / 3;

    float* out_val  = (float*)d_out;        // (B, 1)
    float* out_feat = out_val + B;          // (B, 256)

    // --- counting sort by full cell id ---
    hist_kernel<<<(B + 255) / 256, 256>>>(x, B);
    scan_block_kernel<<<NCELLS / 1024, 1024>>>();
    finalize_kernel<<<NCELLS / 256, 256>>>(B);
    scatter_kernel<<<(B + 255) / 256, 256>>>(x, B);

    // --- scalar grid_value path: thread per point, sorted (coalesced) ---
    gridval_kernel<<<(B + 255) / 256, 256>>>(grid_value, out_val, B);

    // --- feature gather: warp per CELL, full same-cell sharing ---
    int warps_per_block = 4;                 // 128 threads
    int blocks = (NCELLS + warps_per_block - 1) / warps_per_block;
    trilerp_kernel<<<blocks, 128>>>(grid_feature, out_feat);
}